// round 9
// baseline (speedup 1.0000x reference)
#include <cuda_runtime.h>
#include <cstdint>
#include <cstring>
#include <cmath>

#define NE 200000
#define NA 20000
#define KC 32

// ---------------------------------------------------------------------------
// Pooled scratch (concat layout): L0 [NA][1][96], L1 [NA][3][128], L2 [NA][5][128]
// ---------------------------------------------------------------------------
__device__ __align__(16) float g_pool0[NA * 96];
__device__ __align__(16) float g_pool1[NA * 3 * 128];
__device__ __align__(16) float g_pool2[NA * 5 * 128];

// CG constants passed by value (2460 B < 4KB param limit)
struct CgParam { float v[615]; };

// Offsets of CG tensors in numpy-dict generation order (l1,l2,L):
// (0,0,0)@0 (0,1,1)@1 (0,2,2)@10 (1,0,1)@35 (1,1,0)@44 (1,1,1)@53* (1,1,2)@80
// (1,2,1)@125 (1,2,2)@170* (2,0,2)@245 (2,1,1)@270 (2,1,2)@315* (2,2,0)@390
// (2,2,1)@415* (2,2,2)@490   (* = odd parity, unused)

// ---------------------------------------------------------------------------
// Host-side bit-exact replication of np.random.default_rng(42).normal(...)
// ---------------------------------------------------------------------------
namespace cgen {

typedef unsigned __int128 u128;

struct Pcg64 {
    u128 state, inc;
    uint64_t next() {
        const u128 MUL = (((u128)0x2360ed051fc65da4ULL) << 64) | 0x4385df649fccf645ULL;
        state = state * MUL + inc;
        uint64_t hi = (uint64_t)(state >> 64);
        uint64_t lo = (uint64_t)state;
        uint64_t v  = hi ^ lo;
        unsigned rot = (unsigned)(state >> 122);
        return (v >> rot) | (v << ((64u - rot) & 63u));
    }
    double nextd() { return (double)(next() >> 11) * (1.0 / 9007199254740992.0); }
};

static float    h_cg[615];
static CgParam  h_cgp;

struct Init {
    uint64_t zki[256];
    double   zwi[256], zfi[256];
    Pcg64    g;

    double znorm() {
        const double NOR_R = 3.6541528853610088;
        const double NOR_INV_R = 0.27366123732975828;
        for (;;) {
            uint64_t r = g.next();
            int idx = (int)(r & 0xff);
            r >>= 8;
            int sign = (int)(r & 1);
            uint64_t rabs = (r >> 1) & 0x000fffffffffffffULL;
            double x = (double)rabs * zwi[idx];
            if (sign) x = -x;
            if (rabs < zki[idx]) return x;
            if (idx == 0) {
                double xx, yy;
                do {
                    xx = -NOR_INV_R * std::log1p(-g.nextd());
                    yy = -std::log1p(-g.nextd());
                } while (yy + yy <= xx * xx);
                return ((rabs >> 8) & 1) ? -(NOR_R + xx) : NOR_R + xx;
            } else {
                if ((zfi[idx - 1] - zfi[idx]) * g.nextd() + zfi[idx] <
                    std::exp(-0.5 * x * x))
                    return x;
            }
        }
    }

    Init() {
        // ---- SeedSequence(42), pool_size=4 ----
        uint32_t pool[4];
        uint32_t hc = 0x43b0d7e5u;
        auto hashmix = [&hc](uint32_t v) -> uint32_t {
            v ^= hc; hc *= 0x931e8875u; v *= hc; v ^= v >> 16; return v;
        };
        auto mix = [](uint32_t x, uint32_t y) -> uint32_t {
            uint32_t r = x * 0xca01f9ddu - y * 0x4973f715u; r ^= r >> 16; return r;
        };
        pool[0] = hashmix(42u);
        pool[1] = hashmix(0u);
        pool[2] = hashmix(0u);
        pool[3] = hashmix(0u);
        for (int s = 0; s < 4; s++)
            for (int d = 0; d < 4; d++)
                if (s != d) pool[d] = mix(pool[d], hashmix(pool[s]));

        // ---- generate_state(4, uint64) ----
        uint32_t hc2 = 0x8b51f9ddu;
        uint32_t st32[8];
        for (int i = 0; i < 8; i++) {
            uint32_t v = pool[i & 3];
            v ^= hc2; hc2 *= 0x58f38dedu; v *= hc2; v ^= v >> 16;
            st32[i] = v;
        }
        uint64_t s64[4];
        for (int i = 0; i < 4; i++)
            s64[i] = (uint64_t)st32[2 * i] | ((uint64_t)st32[2 * i + 1] << 32);

        // ---- PCG64 seeding (seed[0]=high word) ----
        u128 initstate = (((u128)s64[0]) << 64) | s64[1];
        u128 initseq   = (((u128)s64[2]) << 64) | s64[3];
        const u128 MUL = (((u128)0x2360ed051fc65da4ULL) << 64) | 0x4385df649fccf645ULL;
        g.inc = (initseq << 1) | 1;
        g.state = 0;
        g.state = g.state * MUL + g.inc;
        g.state += initstate;
        g.state = g.state * MUL + g.inc;

        // ---- ziggurat tables (256 layers, 52-bit mantissa) ----
        const double r = 3.6541528853610088;
        const double M52 = 4503599627370496.0; // 2^52
        double f_r = std::exp(-0.5 * r * r);
        double V = r * f_r + 1.2533141373155003 * std::erfc(r * 0.7071067811865476);
        double q = V / f_r;
        zki[0] = (uint64_t)((r / q) * M52);
        zki[1] = 0;
        zwi[0] = q / M52; zwi[255] = r / M52;
        zfi[0] = 1.0;     zfi[255] = f_r;
        double dn = r, tn = r;
        for (int i = 254; i >= 1; i--) {
            dn = std::sqrt(-2.0 * std::log(V / dn + std::exp(-0.5 * dn * dn)));
            zki[i + 1] = (uint64_t)((dn / tn) * M52);
            tn = dn;
            zfi[i] = std::exp(-0.5 * dn * dn);
            zwi[i] = dn / M52;
        }

        // ---- draw all 15 CG tensors in dict order (including odd-parity) ----
        int pos = 0;
        for (int l1 = 0; l1 <= 2; l1++)
            for (int l2 = 0; l2 <= 2; l2++) {
                int lo = l1 > l2 ? l1 - l2 : l2 - l1;
                int hi = (l1 + l2 < 2) ? (l1 + l2) : 2;
                for (int L = lo; L <= hi; L++) {
                    int n = (2 * l1 + 1) * (2 * l2 + 1) * (2 * L + 1);
                    for (int i = 0; i < n; i++)
                        h_cg[pos++] = (float)(znorm() * 0.3);
                }
            }
        std::memcpy(h_cgp.v, h_cg, sizeof(h_cg));
    }
};
static Init g_init;

} // namespace cgen

// ---------------------------------------------------------------------------
// Kernel 0: zero the pooled scratch
// ---------------------------------------------------------------------------
__global__ void zero_kernel() {
    size_t i = (size_t)blockIdx.x * blockDim.x + threadIdx.x;
    size_t stride = (size_t)gridDim.x * blockDim.x;
    float4 z = make_float4(0.f, 0.f, 0.f, 0.f);
    float4* a0 = (float4*)g_pool0;
    float4* a1 = (float4*)g_pool1;
    float4* a2 = (float4*)g_pool2;
    for (size_t j = i; j < (size_t)NA * 96 / 4;      j += stride) a0[j] = z;
    for (size_t j = i; j < (size_t)NA * 3 * 128 / 4; j += stride) a1[j] = z;
    for (size_t j = i; j < (size_t)NA * 5 * 128 / 4; j += stride) a2[j] = z;
}

// ---------------------------------------------------------------------------
// Kernel 1: per-edge CG contractions + atomic scatter into pooled concat
// warp = edge, lane = channel k
// ---------------------------------------------------------------------------
__global__ void __launch_bounds__(256) edge_kernel(
    CgParam cgp,
    const float* __restrict__ radial,
    const float* __restrict__ sh0, const float* __restrict__ sh1,
    const float* __restrict__ sh2,
    const float* __restrict__ feat0, const float* __restrict__ feat1,
    const float* __restrict__ feat2,
    const int* __restrict__ centers, const int* __restrict__ neighbors)
{
    __shared__ float scg[615];
    for (int i = threadIdx.x; i < 615; i += 256) scg[i] = cgp.v[i];
    __syncthreads();

    const int k  = threadIdx.x & 31;
    int gw = blockIdx.x * 8 + (threadIdx.x >> 5);
    const int nw = gridDim.x * 8;

    for (int e = gw; e < NE; e += nw) {
        const int ctr = centers[e];
        const int nb  = neighbors[e];

        const float r0 = radial[(size_t)e * KC + k];
        const float r1 = radial[(size_t)NE * KC + (size_t)e * KC + k];
        const float r2 = radial[2 * (size_t)NE * KC + (size_t)e * KC + k];

        const float t10 = __ldg(sh0 + e) * r0;
        float t11[3], t12[5];
#pragma unroll
        for (int a = 0; a < 3; a++) t11[a] = __ldg(sh1 + 3 * e + a) * r1;
#pragma unroll
        for (int a = 0; a < 5; a++) t12[a] = __ldg(sh2 + 5 * e + a) * r2;

        const float f0 = feat0[(size_t)nb * KC + k];
        float f1[3], f2[5];
#pragma unroll
        for (int a = 0; a < 3; a++) f1[a] = feat1[((size_t)nb * 3 + a) * KC + k];
#pragma unroll
        for (int a = 0; a < 5; a++) f2[a] = feat2[((size_t)nb * 5 + a) * KC + k];

        // reused pair products
        float P11[9], P22[25];
#pragma unroll
        for (int a = 0; a < 3; a++)
#pragma unroll
            for (int b = 0; b < 3; b++) P11[a * 3 + b] = t11[a] * f1[b];
#pragma unroll
        for (int a = 0; a < 5; a++)
#pragma unroll
            for (int b = 0; b < 5; b++) P22[a * 5 + b] = t12[a] * f2[b];

        float* p0 = g_pool0 + (size_t)ctr * 96 + k;
        float* p1 = g_pool1 + (size_t)ctr * 384 + k;
        float* p2 = g_pool2 + (size_t)ctr * 640 + k;

        // ---------------- L = 0 (cols: c*32) ----------------
        atomicAdd(p0 + 0, scg[0] * (t10 * f0));                 // (0,0,0) c0
        {
            float v = 0.f;                                      // (1,1,0) c1
#pragma unroll
            for (int i = 0; i < 9; i++) v += P11[i] * scg[44 + i];
            atomicAdd(p0 + 32, v);
        }
        {
            float v = 0.f;                                      // (2,2,0) c2
#pragma unroll
            for (int i = 0; i < 25; i++) v += P22[i] * scg[390 + i];
            atomicAdd(p0 + 64, v);
        }

        // ---------------- L = 1 (element: M*128 + c*32) ----------------
        {
            float q01[3], q10[3];
#pragma unroll
            for (int b = 0; b < 3; b++) q01[b] = t10 * f1[b];
#pragma unroll
            for (int a = 0; a < 3; a++) q10[a] = t11[a] * f0;
            float q12[15], q21[15];
#pragma unroll
            for (int a = 0; a < 3; a++)
#pragma unroll
                for (int b = 0; b < 5; b++) q12[a * 5 + b] = t11[a] * f2[b];
#pragma unroll
            for (int a = 0; a < 5; a++)
#pragma unroll
                for (int b = 0; b < 3; b++) q21[a * 3 + b] = t12[a] * f1[b];

#pragma unroll
            for (int M = 0; M < 3; M++) {
                float v0 = 0.f, v1 = 0.f, v2 = 0.f, v3 = 0.f;
#pragma unroll
                for (int b = 0; b < 3; b++) v0 += q01[b] * scg[1 + b * 3 + M];   // (0,1,1) c0
#pragma unroll
                for (int a = 0; a < 3; a++) v1 += q10[a] * scg[35 + a * 3 + M];  // (1,0,1) c1
#pragma unroll
                for (int i = 0; i < 15; i++) v2 += q12[i] * scg[125 + i * 3 + M];// (1,2,1) c2
#pragma unroll
                for (int i = 0; i < 15; i++) v3 += q21[i] * scg[270 + i * 3 + M];// (2,1,1) c3
                atomicAdd(p1 + M * 128 + 0,  v0);
                atomicAdd(p1 + M * 128 + 32, v1);
                atomicAdd(p1 + M * 128 + 64, v2);
                atomicAdd(p1 + M * 128 + 96, v3);
            }
        }

        // ---------------- L = 2 (element: M*128 + c*32) ----------------
        {
            float q02[5], q20[5];
#pragma unroll
            for (int b = 0; b < 5; b++) q02[b] = t10 * f2[b];
#pragma unroll
            for (int a = 0; a < 5; a++) q20[a] = t12[a] * f0;

#pragma unroll
            for (int M = 0; M < 5; M++) {
                float v0 = 0.f, v1 = 0.f, v2 = 0.f, v3 = 0.f;
#pragma unroll
                for (int b = 0; b < 5; b++) v0 += q02[b] * scg[10 + b * 5 + M];  // (0,2,2) c0
#pragma unroll
                for (int i = 0; i < 9; i++) v1 += P11[i] * scg[80 + i * 5 + M];  // (1,1,2) c1
#pragma unroll
                for (int a = 0; a < 5; a++) v2 += q20[a] * scg[245 + a * 5 + M]; // (2,0,2) c2
#pragma unroll
                for (int i = 0; i < 25; i++) v3 += P22[i] * scg[490 + i * 5 + M];// (2,2,2) c3
                atomicAdd(p2 + M * 128 + 0,  v0);
                atomicAdd(p2 + M * 128 + 32, v1);
                atomicAdd(p2 + M * 128 + 64, v2);
                atomicAdd(p2 + M * 128 + 96, v3);
            }
        }
    }
}

// ---------------------------------------------------------------------------
// Kernel 2: per-atom linear + bias, *0.1, + residual feat
// 9 warps/block: warp 0 -> L0 row, warps 1-3 -> L1 rows, warps 4-8 -> L2 rows
// ---------------------------------------------------------------------------
__global__ void __launch_bounds__(288) atom_kernel(
    const float* __restrict__ feat0, const float* __restrict__ feat1,
    const float* __restrict__ feat2,
    const float* __restrict__ W0, const float* __restrict__ b0,
    const float* __restrict__ W1, const float* __restrict__ b1,
    const float* __restrict__ W2, const float* __restrict__ b2,
    float* __restrict__ out)
{
    // transposed weights: wt[k][j], pitches chosen for conflict-free LDS.128
    __shared__ __align__(16) float wt0[32 * 100];
    __shared__ __align__(16) float wt1[32 * 132];
    __shared__ __align__(16) float wt2[32 * 132];
    __shared__ float bsh[96];

    for (int i = threadIdx.x; i < 96 * 32; i += 288)
        wt0[(i & 31) * 100 + (i >> 5)] = W0[i];
    for (int i = threadIdx.x; i < 128 * 32; i += 288)
        wt1[(i & 31) * 132 + (i >> 5)] = W1[i];
    for (int i = threadIdx.x; i < 128 * 32; i += 288)
        wt2[(i & 31) * 132 + (i >> 5)] = W2[i];
    if (threadIdx.x < 32) {
        bsh[threadIdx.x]      = b0[threadIdx.x];
        bsh[32 + threadIdx.x] = b1[threadIdx.x];
        bsh[64 + threadIdx.x] = b2[threadIdx.x];
    }
    __syncthreads();

    const int w = threadIdx.x >> 5;
    const int k = threadIdx.x & 31;

    for (int atom = blockIdx.x; atom < NA; atom += gridDim.x) {
        float acc = 0.f;
        if (w == 0) {
            const float4* pr = reinterpret_cast<const float4*>(g_pool0 + (size_t)atom * 96);
            const float4* wr = reinterpret_cast<const float4*>(wt0 + k * 100);
#pragma unroll
            for (int j = 0; j < 24; j++) {
                float4 p = pr[j], wv = wr[j];
                acc += p.x * wv.x + p.y * wv.y + p.z * wv.z + p.w * wv.w;
            }
            int o = atom * 32 + k;
            out[o] = (acc + bsh[k]) * 0.1f + feat0[o];
        } else if (w <= 3) {
            int M = w - 1;
            const float4* pr = reinterpret_cast<const float4*>(g_pool1 + ((size_t)atom * 3 + M) * 128);
            const float4* wr = reinterpret_cast<const float4*>(wt1 + k * 132);
#pragma unroll
            for (int j = 0; j < 32; j++) {
                float4 p = pr[j], wv = wr[j];
                acc += p.x * wv.x + p.y * wv.y + p.z * wv.z + p.w * wv.w;
            }
            int o = (atom * 3 + M) * 32 + k;
            out[NA * 32 + o] = (acc + bsh[32 + k]) * 0.1f + feat1[o];
        } else {
            int M = w - 4;
            const float4* pr = reinterpret_cast<const float4*>(g_pool2 + ((size_t)atom * 5 + M) * 128);
            const float4* wr = reinterpret_cast<const float4*>(wt2 + k * 132);
#pragma unroll
            for (int j = 0; j < 32; j++) {
                float4 p = pr[j], wv = wr[j];
                acc += p.x * wv.x + p.y * wv.y + p.z * wv.z + p.w * wv.w;
            }
            int o = (atom * 5 + M) * 32 + k;
            out[NA * 32 + NA * 96 + o] = (acc + bsh[64 + k]) * 0.1f + feat2[o];
        }
    }
}

// ---------------------------------------------------------------------------
// Launcher
// ---------------------------------------------------------------------------
extern "C" void kernel_launch(void* const* d_in, const int* in_sizes, int n_in,
                              void* d_out, int out_size) {
    (void)in_sizes; (void)n_in; (void)out_size;
    const float* radial = (const float*)d_in[0];
    const float* sh0    = (const float*)d_in[1];
    const float* sh1    = (const float*)d_in[2];
    const float* sh2    = (const float*)d_in[3];
    const float* feat0  = (const float*)d_in[4];
    const float* feat1  = (const float*)d_in[5];
    const float* feat2  = (const float*)d_in[6];
    const float* W0     = (const float*)d_in[7];
    const float* b0     = (const float*)d_in[8];
    const float* W1     = (const float*)d_in[9];
    const float* b1     = (const float*)d_in[10];
    const float* W2     = (const float*)d_in[11];
    const float* b2     = (const float*)d_in[12];
    const int* centers   = (const int*)d_in[13];
    const int* neighbors = (const int*)d_in[14];
    float* out = (float*)d_out;

    zero_kernel<<<1480, 256>>>();
    edge_kernel<<<6250, 256>>>(cgen::h_cgp, radial, sh0, sh1, sh2,
                               feat0, feat1, feat2, centers, neighbors);
    atom_kernel<<<1184, 288>>>(feat0, feat1, feat2,
                               W0, b0, W1, b1, W2, b2, out);
}

// round 10
// speedup vs baseline: 1.2741x; 1.2741x over previous
#include <cuda_runtime.h>
#include <cstdint>
#include <cstring>
#include <cmath>

#define NE 200000
#define NA 20000
#define KC 32

// ---------------------------------------------------------------------------
// Pooled scratch (concat layout): L0 [NA][1][96], L1 [NA][3][128], L2 [NA][5][128]
// ---------------------------------------------------------------------------
__device__ __align__(16) float g_pool0[NA * 96];
__device__ __align__(16) float g_pool1[NA * 3 * 128];
__device__ __align__(16) float g_pool2[NA * 5 * 128];

// CSR over centers
__device__ int g_count[NA];
__device__ int g_off[NA];
__device__ int g_cursor[NA];
__device__ int g_eid[NE];

// CG constants passed by value (2460 B < 4KB param limit)
struct CgParam { float v[615]; };

// Offsets of CG tensors in numpy-dict generation order (l1,l2,L):
// (0,0,0)@0 (0,1,1)@1 (0,2,2)@10 (1,0,1)@35 (1,1,0)@44 (1,1,1)@53* (1,1,2)@80
// (1,2,1)@125 (1,2,2)@170* (2,0,2)@245 (2,1,1)@270 (2,1,2)@315* (2,2,0)@390
// (2,2,1)@415* (2,2,2)@490   (* = odd parity, unused)

// ---------------------------------------------------------------------------
// Host-side bit-exact replication of np.random.default_rng(42).normal(...)
// ---------------------------------------------------------------------------
namespace cgen {

typedef unsigned __int128 u128;

struct Pcg64 {
    u128 state, inc;
    uint64_t next() {
        const u128 MUL = (((u128)0x2360ed051fc65da4ULL) << 64) | 0x4385df649fccf645ULL;
        state = state * MUL + inc;
        uint64_t hi = (uint64_t)(state >> 64);
        uint64_t lo = (uint64_t)state;
        uint64_t v  = hi ^ lo;
        unsigned rot = (unsigned)(state >> 122);
        return (v >> rot) | (v << ((64u - rot) & 63u));
    }
    double nextd() { return (double)(next() >> 11) * (1.0 / 9007199254740992.0); }
};

static float    h_cg[615];
static CgParam  h_cgp;

struct Init {
    uint64_t zki[256];
    double   zwi[256], zfi[256];
    Pcg64    g;

    double znorm() {
        const double NOR_R = 3.6541528853610088;
        const double NOR_INV_R = 0.27366123732975828;
        for (;;) {
            uint64_t r = g.next();
            int idx = (int)(r & 0xff);
            r >>= 8;
            int sign = (int)(r & 1);
            uint64_t rabs = (r >> 1) & 0x000fffffffffffffULL;
            double x = (double)rabs * zwi[idx];
            if (sign) x = -x;
            if (rabs < zki[idx]) return x;
            if (idx == 0) {
                double xx, yy;
                do {
                    xx = -NOR_INV_R * std::log1p(-g.nextd());
                    yy = -std::log1p(-g.nextd());
                } while (yy + yy <= xx * xx);
                return ((rabs >> 8) & 1) ? -(NOR_R + xx) : NOR_R + xx;
            } else {
                if ((zfi[idx - 1] - zfi[idx]) * g.nextd() + zfi[idx] <
                    std::exp(-0.5 * x * x))
                    return x;
            }
        }
    }

    Init() {
        // ---- SeedSequence(42), pool_size=4 ----
        uint32_t pool[4];
        uint32_t hc = 0x43b0d7e5u;
        auto hashmix = [&hc](uint32_t v) -> uint32_t {
            v ^= hc; hc *= 0x931e8875u; v *= hc; v ^= v >> 16; return v;
        };
        auto mix = [](uint32_t x, uint32_t y) -> uint32_t {
            uint32_t r = x * 0xca01f9ddu - y * 0x4973f715u; r ^= r >> 16; return r;
        };
        pool[0] = hashmix(42u);
        pool[1] = hashmix(0u);
        pool[2] = hashmix(0u);
        pool[3] = hashmix(0u);
        for (int s = 0; s < 4; s++)
            for (int d = 0; d < 4; d++)
                if (s != d) pool[d] = mix(pool[d], hashmix(pool[s]));

        // ---- generate_state(4, uint64) ----
        uint32_t hc2 = 0x8b51f9ddu;
        uint32_t st32[8];
        for (int i = 0; i < 8; i++) {
            uint32_t v = pool[i & 3];
            v ^= hc2; hc2 *= 0x58f38dedu; v *= hc2; v ^= v >> 16;
            st32[i] = v;
        }
        uint64_t s64[4];
        for (int i = 0; i < 4; i++)
            s64[i] = (uint64_t)st32[2 * i] | ((uint64_t)st32[2 * i + 1] << 32);

        // ---- PCG64 seeding (seed[0]=high word) ----
        u128 initstate = (((u128)s64[0]) << 64) | s64[1];
        u128 initseq   = (((u128)s64[2]) << 64) | s64[3];
        const u128 MUL = (((u128)0x2360ed051fc65da4ULL) << 64) | 0x4385df649fccf645ULL;
        g.inc = (initseq << 1) | 1;
        g.state = 0;
        g.state = g.state * MUL + g.inc;
        g.state += initstate;
        g.state = g.state * MUL + g.inc;

        // ---- ziggurat tables (256 layers, 52-bit mantissa) ----
        const double r = 3.6541528853610088;
        const double M52 = 4503599627370496.0; // 2^52
        double f_r = std::exp(-0.5 * r * r);
        double V = r * f_r + 1.2533141373155003 * std::erfc(r * 0.7071067811865476);
        double q = V / f_r;
        zki[0] = (uint64_t)((r / q) * M52);
        zki[1] = 0;
        zwi[0] = q / M52; zwi[255] = r / M52;
        zfi[0] = 1.0;     zfi[255] = f_r;
        double dn = r, tn = r;
        for (int i = 254; i >= 1; i--) {
            dn = std::sqrt(-2.0 * std::log(V / dn + std::exp(-0.5 * dn * dn)));
            zki[i + 1] = (uint64_t)((dn / tn) * M52);
            tn = dn;
            zfi[i] = std::exp(-0.5 * dn * dn);
            zwi[i] = dn / M52;
        }

        // ---- draw all 15 CG tensors in dict order (including odd-parity) ----
        int pos = 0;
        for (int l1 = 0; l1 <= 2; l1++)
            for (int l2 = 0; l2 <= 2; l2++) {
                int lo = l1 > l2 ? l1 - l2 : l2 - l1;
                int hi = (l1 + l2 < 2) ? (l1 + l2) : 2;
                for (int L = lo; L <= hi; L++) {
                    int n = (2 * l1 + 1) * (2 * l2 + 1) * (2 * L + 1);
                    for (int i = 0; i < n; i++)
                        h_cg[pos++] = (float)(znorm() * 0.3);
                }
            }
        std::memcpy(h_cgp.v, h_cg, sizeof(h_cg));
    }
};
static Init g_init;

} // namespace cgen

// ---------------------------------------------------------------------------
// CSR build kernels
// ---------------------------------------------------------------------------
__global__ void zero_counts_kernel() {
    int i = blockIdx.x * blockDim.x + threadIdx.x;
    if (i < NA) g_count[i] = 0;
}

__global__ void hist_kernel(const int* __restrict__ centers) {
    int e = blockIdx.x * blockDim.x + threadIdx.x;
    if (e < NE) atomicAdd(&g_count[centers[e]], 1);
}

// Single-block exclusive scan over g_count -> g_off (and g_cursor copy).
__global__ void scan_kernel() {
    __shared__ int s[1024];
    const int t = threadIdx.x;
    const int CH = 20;                       // 1024*20 = 20480 >= NA
    int base = t * CH;
    int loc[CH];
    int sum = 0;
#pragma unroll
    for (int i = 0; i < CH; i++) {
        int idx = base + i;
        int c = (idx < NA) ? g_count[idx] : 0;
        loc[i] = sum;
        sum += c;
    }
    s[t] = sum;
    __syncthreads();
    for (int d = 1; d < 1024; d <<= 1) {
        int v = (t >= d) ? s[t - d] : 0;
        __syncthreads();
        s[t] += v;
        __syncthreads();
    }
    int excl = (t == 0) ? 0 : s[t - 1];
#pragma unroll
    for (int i = 0; i < CH; i++) {
        int idx = base + i;
        if (idx < NA) {
            int o = excl + loc[i];
            g_off[idx] = o;
            g_cursor[idx] = o;
        }
    }
}

__global__ void scatter_kernel(const int* __restrict__ centers) {
    int e = blockIdx.x * blockDim.x + threadIdx.x;
    if (e < NE) {
        int p = atomicAdd(&g_cursor[centers[e]], 1);
        g_eid[p] = e;
    }
}

// ---------------------------------------------------------------------------
// Kernel 1: per-ATOM gather. warp = atom, lane = channel k. No atomics.
// Accumulates the 35 pooled values in registers, plain stores into g_pool*.
// ---------------------------------------------------------------------------
__global__ void __launch_bounds__(256) gather_kernel(
    CgParam cgp,
    const float* __restrict__ radial,
    const float* __restrict__ sh0, const float* __restrict__ sh1,
    const float* __restrict__ sh2,
    const float* __restrict__ feat0, const float* __restrict__ feat1,
    const float* __restrict__ feat2,
    const int* __restrict__ neighbors)
{
    __shared__ float scg[615];
    for (int i = threadIdx.x; i < 615; i += 256) scg[i] = cgp.v[i];
    __syncthreads();

    const int k = threadIdx.x & 31;
    const int atom = blockIdx.x * 8 + (threadIdx.x >> 5);
    if (atom >= NA) return;

    const int beg = g_off[atom];
    const int end = beg + g_count[atom];

    float A00 = 0.f, A01 = 0.f, A02 = 0.f;   // L0: c=0..2
    float B[12];                              // L1: [c*3 + M]
    float C[20];                              // L2: [c*5 + M]
#pragma unroll
    for (int i = 0; i < 12; i++) B[i] = 0.f;
#pragma unroll
    for (int i = 0; i < 20; i++) C[i] = 0.f;

    for (int it = beg; it < end; it++) {
        const int e  = g_eid[it];     // uniform -> broadcast
        const int nb = neighbors[e];

        const float r0 = radial[(size_t)e * KC + k];
        const float r1 = radial[(size_t)NE * KC + (size_t)e * KC + k];
        const float r2 = radial[2 * (size_t)NE * KC + (size_t)e * KC + k];

        const float t10 = __ldg(sh0 + e) * r0;
        float t11[3], t12[5];
#pragma unroll
        for (int a = 0; a < 3; a++) t11[a] = __ldg(sh1 + 3 * e + a) * r1;
#pragma unroll
        for (int a = 0; a < 5; a++) t12[a] = __ldg(sh2 + 5 * e + a) * r2;

        const float f0 = feat0[(size_t)nb * KC + k];
        float f1[3], f2[5];
#pragma unroll
        for (int a = 0; a < 3; a++) f1[a] = feat1[((size_t)nb * 3 + a) * KC + k];
#pragma unroll
        for (int a = 0; a < 5; a++) f2[a] = feat2[((size_t)nb * 5 + a) * KC + k];

        // pair products
        float P11[9], P22[25];
#pragma unroll
        for (int a = 0; a < 3; a++)
#pragma unroll
            for (int b = 0; b < 3; b++) P11[a * 3 + b] = t11[a] * f1[b];
#pragma unroll
        for (int a = 0; a < 5; a++)
#pragma unroll
            for (int b = 0; b < 5; b++) P22[a * 5 + b] = t12[a] * f2[b];

        // ---------------- L = 0 ----------------
        A00 = fmaf(scg[0], t10 * f0, A00);                     // (0,0,0)
#pragma unroll
        for (int i = 0; i < 9; i++)  A01 = fmaf(P11[i], scg[44 + i],  A01); // (1,1,0)
#pragma unroll
        for (int i = 0; i < 25; i++) A02 = fmaf(P22[i], scg[390 + i], A02); // (2,2,0)

        // ---------------- L = 1 ----------------
        {
            float q01[3], q10[3];
#pragma unroll
            for (int b = 0; b < 3; b++) q01[b] = t10 * f1[b];
#pragma unroll
            for (int a = 0; a < 3; a++) q10[a] = t11[a] * f0;
            float q12[15], q21[15];
#pragma unroll
            for (int a = 0; a < 3; a++)
#pragma unroll
                for (int b = 0; b < 5; b++) q12[a * 5 + b] = t11[a] * f2[b];
#pragma unroll
            for (int a = 0; a < 5; a++)
#pragma unroll
                for (int b = 0; b < 3; b++) q21[a * 3 + b] = t12[a] * f1[b];

#pragma unroll
            for (int M = 0; M < 3; M++) {
#pragma unroll
                for (int b = 0; b < 3; b++)  B[0 + M] = fmaf(q01[b], scg[1 + b * 3 + M],   B[0 + M]);  // (0,1,1)
#pragma unroll
                for (int a = 0; a < 3; a++)  B[3 + M] = fmaf(q10[a], scg[35 + a * 3 + M],  B[3 + M]);  // (1,0,1)
#pragma unroll
                for (int i = 0; i < 15; i++) B[6 + M] = fmaf(q12[i], scg[125 + i * 3 + M], B[6 + M]);  // (1,2,1)
#pragma unroll
                for (int i = 0; i < 15; i++) B[9 + M] = fmaf(q21[i], scg[270 + i * 3 + M], B[9 + M]);  // (2,1,1)
            }
        }

        // ---------------- L = 2 ----------------
        {
            float q02[5], q20[5];
#pragma unroll
            for (int b = 0; b < 5; b++) q02[b] = t10 * f2[b];
#pragma unroll
            for (int a = 0; a < 5; a++) q20[a] = t12[a] * f0;

#pragma unroll
            for (int M = 0; M < 5; M++) {
#pragma unroll
                for (int b = 0; b < 5; b++)  C[0 + M]  = fmaf(q02[b], scg[10 + b * 5 + M],  C[0 + M]);  // (0,2,2)
#pragma unroll
                for (int i = 0; i < 9; i++)  C[5 + M]  = fmaf(P11[i], scg[80 + i * 5 + M],  C[5 + M]);  // (1,1,2)
#pragma unroll
                for (int a = 0; a < 5; a++)  C[10 + M] = fmaf(q20[a], scg[245 + a * 5 + M], C[10 + M]); // (2,0,2)
#pragma unroll
                for (int i = 0; i < 25; i++) C[15 + M] = fmaf(P22[i], scg[490 + i * 5 + M], C[15 + M]); // (2,2,2)
            }
        }
    }

    // ---- write pooled rows (coalesced, no atomics) ----
    float* p0 = g_pool0 + (size_t)atom * 96 + k;
    p0[0]  = A00;
    p0[32] = A01;
    p0[64] = A02;

    float* p1 = g_pool1 + (size_t)atom * 384 + k;
#pragma unroll
    for (int M = 0; M < 3; M++) {
        p1[M * 128 + 0]  = B[0 + M];
        p1[M * 128 + 32] = B[3 + M];
        p1[M * 128 + 64] = B[6 + M];
        p1[M * 128 + 96] = B[9 + M];
    }

    float* p2 = g_pool2 + (size_t)atom * 640 + k;
#pragma unroll
    for (int M = 0; M < 5; M++) {
        p2[M * 128 + 0]  = C[0 + M];
        p2[M * 128 + 32] = C[5 + M];
        p2[M * 128 + 64] = C[10 + M];
        p2[M * 128 + 96] = C[15 + M];
    }
}

// ---------------------------------------------------------------------------
// Kernel 2: per-atom linear + bias, *0.1, + residual feat
// 9 warps/block: warp 0 -> L0 row, warps 1-3 -> L1 rows, warps 4-8 -> L2 rows
// ---------------------------------------------------------------------------
__global__ void __launch_bounds__(288) atom_kernel(
    const float* __restrict__ feat0, const float* __restrict__ feat1,
    const float* __restrict__ feat2,
    const float* __restrict__ W0, const float* __restrict__ b0,
    const float* __restrict__ W1, const float* __restrict__ b1,
    const float* __restrict__ W2, const float* __restrict__ b2,
    float* __restrict__ out)
{
    // transposed weights: wt[k][j], pitches chosen for conflict-free LDS.128
    __shared__ __align__(16) float wt0[32 * 100];
    __shared__ __align__(16) float wt1[32 * 132];
    __shared__ __align__(16) float wt2[32 * 132];
    __shared__ float bsh[96];

    for (int i = threadIdx.x; i < 96 * 32; i += 288)
        wt0[(i & 31) * 100 + (i >> 5)] = W0[i];
    for (int i = threadIdx.x; i < 128 * 32; i += 288)
        wt1[(i & 31) * 132 + (i >> 5)] = W1[i];
    for (int i = threadIdx.x; i < 128 * 32; i += 288)
        wt2[(i & 31) * 132 + (i >> 5)] = W2[i];
    if (threadIdx.x < 32) {
        bsh[threadIdx.x]      = b0[threadIdx.x];
        bsh[32 + threadIdx.x] = b1[threadIdx.x];
        bsh[64 + threadIdx.x] = b2[threadIdx.x];
    }
    __syncthreads();

    const int w = threadIdx.x >> 5;
    const int k = threadIdx.x & 31;

    for (int atom = blockIdx.x; atom < NA; atom += gridDim.x) {
        float acc = 0.f;
        if (w == 0) {
            const float4* pr = reinterpret_cast<const float4*>(g_pool0 + (size_t)atom * 96);
            const float4* wr = reinterpret_cast<const float4*>(wt0 + k * 100);
#pragma unroll
            for (int j = 0; j < 24; j++) {
                float4 p = pr[j], wv = wr[j];
                acc += p.x * wv.x + p.y * wv.y + p.z * wv.z + p.w * wv.w;
            }
            int o = atom * 32 + k;
            out[o] = (acc + bsh[k]) * 0.1f + feat0[o];
        } else if (w <= 3) {
            int M = w - 1;
            const float4* pr = reinterpret_cast<const float4*>(g_pool1 + ((size_t)atom * 3 + M) * 128);
            const float4* wr = reinterpret_cast<const float4*>(wt1 + k * 132);
#pragma unroll
            for (int j = 0; j < 32; j++) {
                float4 p = pr[j], wv = wr[j];
                acc += p.x * wv.x + p.y * wv.y + p.z * wv.z + p.w * wv.w;
            }
            int o = (atom * 3 + M) * 32 + k;
            out[NA * 32 + o] = (acc + bsh[32 + k]) * 0.1f + feat1[o];
        } else {
            int M = w - 4;
            const float4* pr = reinterpret_cast<const float4*>(g_pool2 + ((size_t)atom * 5 + M) * 128);
            const float4* wr = reinterpret_cast<const float4*>(wt2 + k * 132);
#pragma unroll
            for (int j = 0; j < 32; j++) {
                float4 p = pr[j], wv = wr[j];
                acc += p.x * wv.x + p.y * wv.y + p.z * wv.z + p.w * wv.w;
            }
            int o = (atom * 5 + M) * 32 + k;
            out[NA * 32 + NA * 96 + o] = (acc + bsh[64 + k]) * 0.1f + feat2[o];
        }
    }
}

// ---------------------------------------------------------------------------
// Launcher
// ---------------------------------------------------------------------------
extern "C" void kernel_launch(void* const* d_in, const int* in_sizes, int n_in,
                              void* d_out, int out_size) {
    (void)in_sizes; (void)n_in; (void)out_size;
    const float* radial = (const float*)d_in[0];
    const float* sh0    = (const float*)d_in[1];
    const float* sh1    = (const float*)d_in[2];
    const float* sh2    = (const float*)d_in[3];
    const float* feat0  = (const float*)d_in[4];
    const float* feat1  = (const float*)d_in[5];
    const float* feat2  = (const float*)d_in[6];
    const float* W0     = (const float*)d_in[7];
    const float* b0     = (const float*)d_in[8];
    const float* W1     = (const float*)d_in[9];
    const float* b1     = (const float*)d_in[10];
    const float* W2     = (const float*)d_in[11];
    const float* b2     = (const float*)d_in[12];
    const int* centers   = (const int*)d_in[13];
    const int* neighbors = (const int*)d_in[14];
    float* out = (float*)d_out;

    // CSR build over centers
    zero_counts_kernel<<<(NA + 255) / 256, 256>>>();
    hist_kernel<<<(NE + 255) / 256, 256>>>(centers);
    scan_kernel<<<1, 1024>>>();
    scatter_kernel<<<(NE + 255) / 256, 256>>>(centers);

    // gather: warp per atom (2500 * 8 warps = 20000 atoms)
    gather_kernel<<<2500, 256>>>(cgen::h_cgp, radial, sh0, sh1, sh2,
                                 feat0, feat1, feat2, neighbors);

    atom_kernel<<<1184, 288>>>(feat0, feat1, feat2,
                               W0, b0, W1, b1, W2, b2, out);
}